// round 16
// baseline (speedup 1.0000x reference)
#include <cuda_runtime.h>
#include <cuda_bf16.h>
#include <cstdint>

#define Bb 4
#define Nn 8192
#define Ss 2048
#define C1c 128
#define C2c 256
#define CIN 384
#define Hh 256
#define Pp (Bb*Nn)      // 32768
#define PT 256          // P tiles of 128

// ------------------- scratch (device globals; no allocation) -------------------
__device__ float g_pts2t[Bb*Ss*C2c];
__device__ float g_feat[(size_t)Pp*CIN];
__device__ float g_y1[(size_t)Pp*Hh];
__device__ float g_y2[(size_t)Pp*Hh];
__device__ __nv_bfloat16 g_W1H[Hh*CIN];
__device__ __nv_bfloat16 g_W1L[Hh*CIN];
__device__ __nv_bfloat16 g_W2H[Hh*Hh];
__device__ __nv_bfloat16 g_W2L[Hh*Hh];
__device__ float g_partS[2][Hh][PT];
__device__ float g_partQ[2][Hh][PT];
__device__ float g_scale[2][Hh];
__device__ float g_shift[2][Hh];

__device__ __forceinline__ void bf16split(float v, __nv_bfloat16& h, __nv_bfloat16& l) {
    h = __float2bfloat16(v);
    l = __float2bfloat16(v - __bfloat162float(h));
}

__device__ __forceinline__ uint32_t smem_u32(const void* p) {
    uint32_t a;
    asm("{ .reg .u64 t; cvta.to.shared.u64 t, %1; cvt.u32.u64 %0, t; }" : "=r"(a) : "l"(p));
    return a;
}

// packed fp32x2 FMA
__device__ __forceinline__ float2 ffma2(float2 a, float2 b, float2 c) {
    float2 d;
    asm("fma.rn.f32x2 %0, %1, %2, %3;"
        : "=l"(reinterpret_cast<unsigned long long&>(d))
        : "l"(reinterpret_cast<unsigned long long&>(a)),
          "l"(reinterpret_cast<unsigned long long&>(b)),
          "l"(reinterpret_cast<unsigned long long&>(c)));
    return d;
}

// mma.sync m16n8k16 bf16
__device__ __forceinline__ void mma16816(float* c, const uint32_t* a, const uint32_t* b) {
    asm volatile(
        "mma.sync.aligned.m16n8k16.row.col.f32.bf16.bf16.f32 "
        "{%0,%1,%2,%3}, {%4,%5,%6,%7}, {%8,%9}, {%0,%1,%2,%3};"
        : "+f"(c[0]), "+f"(c[1]), "+f"(c[2]), "+f"(c[3])
        : "r"(a[0]), "r"(a[1]), "r"(a[2]), "r"(a[3]), "r"(b[0]), "r"(b[1]));
}

// ldmatrix (sm_75+)
__device__ __forceinline__ void ldsm_x4(uint32_t* r, uint32_t saddr) {
    asm volatile("ldmatrix.sync.aligned.m8n8.x4.shared.b16 {%0,%1,%2,%3}, [%4];"
        : "=r"(r[0]), "=r"(r[1]), "=r"(r[2]), "=r"(r[3]) : "r"(saddr));
}
__device__ __forceinline__ void ldsm_x2(uint32_t* r, uint32_t saddr) {
    asm volatile("ldmatrix.sync.aligned.m8n8.x2.shared.b16 {%0,%1}, [%2];"
        : "=r"(r[0]), "=r"(r[1]) : "r"(saddr));
}

// ------------------- W1/W2 -> bf16 hi/lo (one-time) -------------------
__global__ void wcvt(const float* __restrict__ W1, const float* __restrict__ W2) {
    int i = blockIdx.x * 256 + threadIdx.x;
    if (i < Hh * CIN) bf16split(W1[i], g_W1H[i], g_W1L[i]);
    if (i < Hh * Hh)  bf16split(W2[i], g_W2H[i], g_W2L[i]);
}

// ------------------- transpose points2 [B,C2,S] -> g_pts2t [B,S,C2] -------------------
__global__ void transpose_p2(const float* __restrict__ in) {
    __shared__ float tile[32][33];
    int b = blockIdx.z;
    int n0 = blockIdx.x * 32, c0 = blockIdx.y * 32;
    int tx = threadIdx.x, ty = threadIdx.y;
#pragma unroll
    for (int k = 0; k < 4; k++)
        tile[ty + k * 8][tx] = in[((size_t)b * C2c + c0 + ty + k * 8) * Ss + n0 + tx];
    __syncthreads();
#pragma unroll
    for (int k = 0; k < 4; k++) {
        int n = n0 + ty + k * 8;
        g_pts2t[((size_t)b * Ss + n) * C2c + c0 + tx] = tile[tx][ty + k * 8];
    }
}

// ------------------- transpose points1 [B,C1,N] -> g_feat cols 0..127 (fp32) ----------
__global__ void transpose_p1(const float* __restrict__ in) {
    __shared__ float tile[32][33];
    int b = blockIdx.z;
    int n0 = blockIdx.x * 32, c0 = blockIdx.y * 32;
    int tx = threadIdx.x, ty = threadIdx.y;
#pragma unroll
    for (int k = 0; k < 4; k++)
        tile[ty + k * 8][tx] = in[((size_t)b * C1c + c0 + ty + k * 8) * Nn + n0 + tx];
    __syncthreads();
#pragma unroll
    for (int k = 0; k < 4; k++) {
        int n = n0 + ty + k * 8;
        g_feat[((size_t)b * Nn + n) * CIN + c0 + tx] = tile[tx][ty + k * 8];
    }
}

// ------------------- kNN(3) + interp: 4 queries/warp, f32x2 packed distance -----------
#define INS3(e, i, E0, E1, E2, I0, I1, I2)                         \
    if ((e) < (E2)) {                                              \
        if ((e) < (E1)) {                                          \
            E2 = E1; I2 = I1;                                      \
            if ((e) < (E0)) { E1 = E0; I1 = I0; E0 = (e); I0 = (i); } \
            else            { E1 = (e); I1 = (i); }                \
        } else { E2 = (e); I2 = (i); }                             \
    }

__global__ void knn_interp(const float* __restrict__ xyz1, const float* __restrict__ xyz2) {
    __shared__ float4 c4[Ss];
    int b = blockIdx.y;
    int n_base = blockIdx.x * 32;

    const float* x2 = xyz2 + (size_t)b * Ss * 3;
    for (int s = threadIdx.x; s < Ss; s += blockDim.x) {
        float x = x2[s * 3 + 0], y = x2[s * 3 + 1], z = x2[s * 3 + 2];
        c4[s] = make_float4(x, y, z, fmaf(x, x, fmaf(y, y, z * z)));
    }
    __syncthreads();

    int warp = threadIdx.x >> 5, lane = threadIdx.x & 31;
    int n0 = n_base + warp * 4;

    float qx[4], qy[4], qz[4], qsq[4];
#pragma unroll
    for (int q = 0; q < 4; q++) {
        const float* xq = xyz1 + ((size_t)b * Nn + n0 + q) * 3;
        qx[q] = xq[0]; qy[q] = xq[1]; qz[q] = xq[2];
        qsq[q] = fmaf(qx[q], qx[q], fmaf(qy[q], qy[q], qz[q] * qz[q]));
    }
    float2 X01 = {qx[0], qx[1]}, Y01 = {qy[0], qy[1]}, Z01 = {qz[0], qz[1]};
    float2 X23 = {qx[2], qx[3]}, Y23 = {qy[2], qy[3]}, Z23 = {qz[2], qz[3]};
    const float2 M2 = {-2.f, -2.f};
    const float2 Z2 = {0.f, 0.f};

    float E[4][3]; int I[4][3];
#pragma unroll
    for (int q = 0; q < 4; q++) {
        E[q][0] = E[q][1] = E[q][2] = 3.4e38f;
        I[q][0] = I[q][1] = I[q][2] = 0x7fffffff;
    }

#pragma unroll 4
    for (int s = lane; s < Ss; s += 32) {
        float4 c = c4[s];
        float2 CX = {c.x, c.x}, CY = {c.y, c.y}, CZ = {c.z, c.z}, CW = {c.w, c.w};
        float2 d01 = ffma2(X01, CX, ffma2(Y01, CY, ffma2(Z01, CZ, Z2)));
        float2 d23 = ffma2(X23, CX, ffma2(Y23, CY, ffma2(Z23, CZ, Z2)));
        float2 e01 = ffma2(M2, d01, CW);
        float2 e23 = ffma2(M2, d23, CW);
        INS3(e01.x, s, E[0][0], E[0][1], E[0][2], I[0][0], I[0][1], I[0][2]);
        INS3(e01.y, s, E[1][0], E[1][1], E[1][2], I[1][0], I[1][1], I[1][2]);
        INS3(e23.x, s, E[2][0], E[2][1], E[2][2], I[2][0], I[2][1], I[2][2]);
        INS3(e23.y, s, E[3][0], E[3][1], E[3][2], I[3][0], I[3][1], I[3][2]);
    }

#pragma unroll
    for (int q = 0; q < 4; q++) {
        int n = n0 + q;
        float be[3]; int bi[3];
        float h = E[q][0]; int hi = I[q][0]; int slot = 0;
        for (int k = 0; k < 3; k++) {
            float v = h; int vi = hi;
#pragma unroll
            for (int off = 16; off; off >>= 1) {
                float ov = __shfl_xor_sync(0xffffffffu, v, off);
                int   oi = __shfl_xor_sync(0xffffffffu, vi, off);
                if (ov < v || (ov == v && oi < vi)) { v = ov; vi = oi; }
            }
            be[k] = v; bi[k] = vi;
            if (h == v && hi == vi) {
                slot++;
                h  = (slot == 1) ? E[q][1] : E[q][2];
                hi = (slot == 1) ? I[q][1] : I[q][2];
            }
        }
        float d0 = fmaxf(be[0] + qsq[q], 0.f);
        float d1 = fmaxf(be[1] + qsq[q], 0.f);
        float d2 = fmaxf(be[2] + qsq[q], 0.f);
        float r0 = 1.f / (d0 + 1e-8f);
        float r1 = 1.f / (d1 + 1e-8f);
        float r2 = 1.f / (d2 + 1e-8f);
        float inv = 1.f / (r0 + r1 + r2);
        float w0 = r0 * inv, w1 = r1 * inv, w2 = r2 * inv;

        const float* p0 = g_pts2t + ((size_t)b * Ss + bi[0]) * C2c;
        const float* p1 = g_pts2t + ((size_t)b * Ss + bi[1]) * C2c;
        const float* p2 = g_pts2t + ((size_t)b * Ss + bi[2]) * C2c;
        float* f = g_feat + ((size_t)b * Nn + n) * CIN + C1c;
#pragma unroll
        for (int j = 0; j < 8; j++) {
            int c = lane + 32 * j;
            f[c] = w0 * p0[c] + w1 * p1[c] + w2 * p2[c];
        }
    }
}

// ------------------- GEMM via mma.sync bf16x3, k-slice 32, ldmatrix fragments ---------
// __launch_bounds__(512, 2): cap regs at 64 -> 2 resident CTAs/SM (smem 2x84.5KB fits),
// halving wave count (3.46 -> 1.73) and overlapping one CTA's mma with the other's loads.
#define SR 40
#define BUFSZ 20480
#define OFF_AH 0
#define OFF_AL 5120
#define OFF_WH 10240
#define OFF_WL 15360
#define OFF_BIAS  81920
#define OFF_SCALE 82432
#define OFF_SHIFT 83456
#define GSM_BYTES 84480
template <int K, bool APPLY_BN, int LAYER>
__global__ void __launch_bounds__(512, 2) gemm_mma(const float* __restrict__ bias) {
    extern __shared__ char smc[];
    __nv_bfloat16* sm = (__nv_bfloat16*)smc;
    float* bias_s  = (float*)(smc + OFF_BIAS);
    float* scale_s = (float*)(smc + OFF_SCALE);
    float* shift_s = (float*)(smc + OFF_SHIFT);
    const uint32_t sbase = smem_u32(smc);

    const float* A = (LAYER == 0) ? g_feat : g_y1;
    const __nv_bfloat16* WH = (LAYER == 0) ? g_W1H : g_W2H;
    const __nv_bfloat16* WL = (LAYER == 0) ? g_W1L : g_W2L;
    float* C = (LAYER == 0) ? g_y1 : g_y2;

    const int tid = threadIdx.x;
    const int p0 = blockIdx.x * 128;
    const int m0 = blockIdx.y * 128;
    const int NS = K / 32;

    if (tid < 128) bias_s[tid] = bias[m0 + tid];
    if (APPLY_BN && tid < Hh) { scale_s[tid] = g_scale[0][tid]; shift_s[tid] = g_shift[0][tid]; }

    const int wrow = tid >> 2, wp = tid & 3;
    const int wid = tid >> 5, lane = tid & 31;
    const int wm = wid & 3;
    const int wn = wid >> 2;
    const int gid = lane >> 2, tig = lane & 3;

    // ldmatrix lane-address bases
    const int li = lane & 7, lsel = lane >> 3;
    const int aoff0 = (wm * 32 + (lsel & 1) * 8 + li) * SR + (lsel >> 1) * 8;
    const int boff0 = (wn * 32 + li) * SR + ((lane >> 3) & 1) * 8;

    float acc[2][4][4];
#pragma unroll
    for (int a = 0; a < 2; a++)
#pragma unroll
        for (int b = 0; b < 4; b++)
#pragma unroll
            for (int c = 0; c < 4; c++) acc[a][b][c] = 0.f;

    __syncthreads();

    auto cvt4 = [&](float4 v, int kcol, uint2& H, uint2& L) {
        if (APPLY_BN) {
            v.x = fmaxf(fmaf(v.x, scale_s[kcol + 0], shift_s[kcol + 0]), 0.f);
            v.y = fmaxf(fmaf(v.y, scale_s[kcol + 1], shift_s[kcol + 1]), 0.f);
            v.z = fmaxf(fmaf(v.z, scale_s[kcol + 2], shift_s[kcol + 2]), 0.f);
            v.w = fmaxf(fmaf(v.w, scale_s[kcol + 3], shift_s[kcol + 3]), 0.f);
        }
        __nv_bfloat16 h0, h1, h2, h3, l0, l1, l2, l3;
        bf16split(v.x, h0, l0); bf16split(v.y, h1, l1);
        bf16split(v.z, h2, l2); bf16split(v.w, h3, l3);
        __nv_bfloat162 hp0 = {h0, h1}, hp1 = {h2, h3}, lp0 = {l0, l1}, lp1 = {l2, l3};
        H = make_uint2(*(uint32_t*)&hp0, *(uint32_t*)&hp1);
        L = make_uint2(*(uint32_t*)&lp0, *(uint32_t*)&lp1);
    };

    auto store_slice = [&](int kt0, int buf, const float4* pa, uint4 pwh, uint4 pwl) {
        int ob = buf * BUFSZ;
#pragma unroll
        for (int i = 0; i < 2; i++) {
            int idx = tid * 2 + i;
            int row = idx >> 3, c4 = idx & 7;
            uint2 H, L;
            cvt4(pa[i], kt0 + c4 * 4, H, L);
            *(uint2*)&sm[ob + OFF_AH + row * SR + c4 * 4] = H;
            *(uint2*)&sm[ob + OFF_AL + row * SR + c4 * 4] = L;
        }
        *(uint4*)&sm[ob + OFF_WH + wrow * SR + wp * 8] = pwh;
        *(uint4*)&sm[ob + OFF_WL + wrow * SR + wp * 8] = pwl;
    };

    {
        float4 pa[2];
#pragma unroll
        for (int i = 0; i < 2; i++) {
            int idx = tid * 2 + i;
            int row = idx >> 3, c4 = idx & 7;
            pa[i] = *(const float4*)&A[(size_t)(p0 + row) * K + c4 * 4];
        }
        uint4 pwh = *(const uint4*)&WH[(size_t)(m0 + wrow) * K + wp * 8];
        uint4 pwl = *(const uint4*)&WL[(size_t)(m0 + wrow) * K + wp * 8];
        store_slice(0, 0, pa, pwh, pwl);
    }
    __syncthreads();

    for (int ks = 0; ks < NS; ks++) {
        const int buf = ks & 1;
        const uint32_t abase = sbase + (uint32_t)(buf * BUFSZ) * 2;

        float4 pa[2]; uint4 pwh, pwl;
        const bool nxt = (ks + 1 < NS);
        if (nxt) {
            int k0 = (ks + 1) * 32;
#pragma unroll
            for (int i = 0; i < 2; i++) {
                int idx = tid * 2 + i;
                int row = idx >> 3, c4 = idx & 7;
                pa[i] = *(const float4*)&A[(size_t)(p0 + row) * K + k0 + c4 * 4];
            }
            pwh = *(const uint4*)&WH[(size_t)(m0 + wrow) * K + k0 + wp * 8];
            pwl = *(const uint4*)&WL[(size_t)(m0 + wrow) * K + k0 + wp * 8];
        }

#pragma unroll
        for (int kk = 0; kk < 2; kk++) {
            const int co = kk * 16;
            uint32_t aH[2][4], aL[2][4], bH[4][2], bL[4][2];
#pragma unroll
            for (int ma = 0; ma < 2; ma++) {
                uint32_t ao = (uint32_t)(aoff0 + ma * 16 * SR + co) * 2;
                ldsm_x4(aH[ma], abase + (OFF_AH * 2) + ao);
                ldsm_x4(aL[ma], abase + (OFF_AL * 2) + ao);
            }
#pragma unroll
            for (int na = 0; na < 4; na++) {
                uint32_t bo = (uint32_t)(boff0 + na * 8 * SR + co) * 2;
                ldsm_x2(bH[na], abase + (OFF_WH * 2) + bo);
                ldsm_x2(bL[na], abase + (OFF_WL * 2) + bo);
            }
#pragma unroll
            for (int ma = 0; ma < 2; ma++)
#pragma unroll
                for (int na = 0; na < 4; na++) {
                    mma16816(acc[ma][na], aH[ma], bH[na]);
                    mma16816(acc[ma][na], aH[ma], bL[na]);
                    mma16816(acc[ma][na], aL[ma], bH[na]);
                }
        }

        if (nxt) store_slice((ks + 1) * 32, buf ^ 1, pa, pwh, pwl);
        __syncthreads();
    }

    float* stg = (float*)smc;   // [128][132]
#pragma unroll
    for (int ma = 0; ma < 2; ma++)
#pragma unroll
        for (int na = 0; na < 4; na++) {
            int r = wm * 32 + ma * 16 + gid;
            int c = wn * 32 + na * 8 + tig * 2;
            float b0v = bias_s[c], b1v = bias_s[c + 1];
            stg[r * 132 + c]           = acc[ma][na][0] + b0v;
            stg[r * 132 + c + 1]       = acc[ma][na][1] + b1v;
            stg[(r + 8) * 132 + c]     = acc[ma][na][2] + b0v;
            stg[(r + 8) * 132 + c + 1] = acc[ma][na][3] + b1v;
        }
    __syncthreads();
#pragma unroll
    for (int it = 0; it < 8; it++) {
        int idx = tid + it * 512;
        int row = idx >> 5, c4i = idx & 31;
        float4 v = *(const float4*)&stg[row * 132 + c4i * 4];
        *(float4*)&C[(size_t)(p0 + row) * Hh + m0 + c4i * 4] = v;
    }
    if (tid < 128) {
        float s = 0.f, q = 0.f;
#pragma unroll 8
        for (int r = 0; r < 128; r++) {
            float v = stg[r * 132 + tid];
            s += v; q += v * v;
        }
        g_partS[LAYER][m0 + tid][blockIdx.x] = s;
        g_partQ[LAYER][m0 + tid][blockIdx.x] = q;
    }
}

// ------------------- BN stats -> per-channel scale/shift -------------------
template <int LAYER>
__global__ void bnstats(const float* __restrict__ gamma, const float* __restrict__ beta) {
    int m = threadIdx.x;
    float s = 0.f, q = 0.f;
#pragma unroll 8
    for (int i = 0; i < PT; i++) { s += g_partS[LAYER][m][i]; q += g_partQ[LAYER][m][i]; }
    const float invP = 1.f / (float)Pp;
    float mean = s * invP;
    float var = q * invP - mean * mean;
    float sc = gamma[m] * rsqrtf(var + 1e-5f);
    g_scale[LAYER][m] = sc;
    g_shift[LAYER][m] = beta[m] - mean * sc;
}

// ------------------- final: relu(bn2(y2)) -> out [B][256][N] (transpose) -------------
__global__ void bn_out(float* __restrict__ out) {
    __shared__ float tile[32][33];
    int b = blockIdx.z;
    int n0 = blockIdx.x * 32, m0 = blockIdx.y * 32;
    int tx = threadIdx.x, ty = threadIdx.y;
#pragma unroll
    for (int k = 0; k < 4; k++) {
        int nn = ty + k * 8;
        tile[nn][tx] = g_y2[((size_t)b * Nn + n0 + nn) * Hh + m0 + tx];
    }
    __syncthreads();
#pragma unroll
    for (int k = 0; k < 4; k++) {
        int m = m0 + ty + k * 8;
        float v = fmaxf(fmaf(tile[tx][ty + k * 8], g_scale[1][m], g_shift[1][m]), 0.f);
        out[(size_t)b * Hh * Nn + (size_t)m * Nn + n0 + tx] = v;
    }
}

// ------------------- launch -------------------
extern "C" void kernel_launch(void* const* d_in, const int* in_sizes, int n_in,
                              void* d_out, int out_size) {
    const float* xyz1    = (const float*)d_in[0];
    const float* xyz2    = (const float*)d_in[1];
    const float* points1 = (const float*)d_in[2];
    const float* points2 = (const float*)d_in[3];
    const float* W1      = (const float*)d_in[4];
    const float* b1      = (const float*)d_in[5];
    const float* gamma1  = (const float*)d_in[6];
    const float* beta1   = (const float*)d_in[7];
    const float* W2      = (const float*)d_in[8];
    const float* b2      = (const float*)d_in[9];
    const float* gamma2  = (const float*)d_in[10];
    const float* beta2   = (const float*)d_in[11];
    float* out = (float*)d_out;

    cudaFuncSetAttribute(gemm_mma<CIN, false, 0>, cudaFuncAttributeMaxDynamicSharedMemorySize, GSM_BYTES);
    cudaFuncSetAttribute(gemm_mma<Hh, true, 1>,  cudaFuncAttributeMaxDynamicSharedMemorySize, GSM_BYTES);

    dim3 tb(32, 8);
    wcvt<<<(Hh * CIN + 255) / 256, 256>>>(W1, W2);
    transpose_p2<<<dim3(Ss / 32, C2c / 32, Bb), tb>>>(points2);
    transpose_p1<<<dim3(Nn / 32, C1c / 32, Bb), tb>>>(points1);
    knn_interp<<<dim3(Nn / 32, Bb), 256>>>(xyz1, xyz2);
    gemm_mma<CIN, false, 0><<<dim3(PT, 2), 512, GSM_BYTES>>>(b1);
    bnstats<0><<<1, 256>>>(gamma1, beta1);
    gemm_mma<Hh, true, 1><<<dim3(PT, 2), 512, GSM_BYTES>>>(b2);
    bnstats<1><<<1, 256>>>(gamma2, beta2);
    bn_out<<<dim3(Nn / 32, Hh / 32, Bb), tb>>>(out);
    (void)in_sizes; (void)n_in; (void)out_size;
}

// round 17
// speedup vs baseline: 1.1061x; 1.1061x over previous
#include <cuda_runtime.h>
#include <cuda_bf16.h>
#include <cstdint>

#define Bb 4
#define Nn 8192
#define Ss 2048
#define C1c 128
#define C2c 256
#define CIN 384
#define Hh 256
#define Pp (Bb*Nn)      // 32768
#define PT 256          // P tiles of 128

// ------------------- scratch (device globals; no allocation) -------------------
__device__ float g_pts2t[Bb*Ss*C2c];
__device__ float g_feat[(size_t)Pp*CIN];
__device__ float g_y1[(size_t)Pp*Hh];
__device__ float g_y2[(size_t)Pp*Hh];
__device__ __nv_bfloat16 g_W1H[Hh*CIN];
__device__ __nv_bfloat16 g_W1L[Hh*CIN];
__device__ __nv_bfloat16 g_W2H[Hh*Hh];
__device__ __nv_bfloat16 g_W2L[Hh*Hh];
__device__ float g_partS[2][Hh][PT];
__device__ float g_partQ[2][Hh][PT];
__device__ float g_scale[2][Hh];
__device__ float g_shift[2][Hh];

__device__ __forceinline__ void bf16split(float v, __nv_bfloat16& h, __nv_bfloat16& l) {
    h = __float2bfloat16(v);
    l = __float2bfloat16(v - __bfloat162float(h));
}

__device__ __forceinline__ uint32_t smem_u32(const void* p) {
    uint32_t a;
    asm("{ .reg .u64 t; cvta.to.shared.u64 t, %1; cvt.u32.u64 %0, t; }" : "=r"(a) : "l"(p));
    return a;
}

// packed fp32x2 FMA
__device__ __forceinline__ float2 ffma2(float2 a, float2 b, float2 c) {
    float2 d;
    asm("fma.rn.f32x2 %0, %1, %2, %3;"
        : "=l"(reinterpret_cast<unsigned long long&>(d))
        : "l"(reinterpret_cast<unsigned long long&>(a)),
          "l"(reinterpret_cast<unsigned long long&>(b)),
          "l"(reinterpret_cast<unsigned long long&>(c)));
    return d;
}

// mma.sync m16n8k16 bf16
__device__ __forceinline__ void mma16816(float* c, const uint32_t* a, const uint32_t* b) {
    asm volatile(
        "mma.sync.aligned.m16n8k16.row.col.f32.bf16.bf16.f32 "
        "{%0,%1,%2,%3}, {%4,%5,%6,%7}, {%8,%9}, {%0,%1,%2,%3};"
        : "+f"(c[0]), "+f"(c[1]), "+f"(c[2]), "+f"(c[3])
        : "r"(a[0]), "r"(a[1]), "r"(a[2]), "r"(a[3]), "r"(b[0]), "r"(b[1]));
}

// ldmatrix (sm_75+)
__device__ __forceinline__ void ldsm_x4(uint32_t* r, uint32_t saddr) {
    asm volatile("ldmatrix.sync.aligned.m8n8.x4.shared.b16 {%0,%1,%2,%3}, [%4];"
        : "=r"(r[0]), "=r"(r[1]), "=r"(r[2]), "=r"(r[3]) : "r"(saddr));
}
__device__ __forceinline__ void ldsm_x2(uint32_t* r, uint32_t saddr) {
    asm volatile("ldmatrix.sync.aligned.m8n8.x2.shared.b16 {%0,%1}, [%2];"
        : "=r"(r[0]), "=r"(r[1]) : "r"(saddr));
}

// ------------------- W1/W2 -> bf16 hi/lo (one-time) -------------------
__global__ void wcvt(const float* __restrict__ W1, const float* __restrict__ W2) {
    int i = blockIdx.x * 256 + threadIdx.x;
    if (i < Hh * CIN) bf16split(W1[i], g_W1H[i], g_W1L[i]);
    if (i < Hh * Hh)  bf16split(W2[i], g_W2H[i], g_W2L[i]);
}

// ------------------- transpose points2 [B,C2,S] -> g_pts2t [B,S,C2] -------------------
__global__ void transpose_p2(const float* __restrict__ in) {
    __shared__ float tile[32][33];
    int b = blockIdx.z;
    int n0 = blockIdx.x * 32, c0 = blockIdx.y * 32;
    int tx = threadIdx.x, ty = threadIdx.y;
#pragma unroll
    for (int k = 0; k < 4; k++)
        tile[ty + k * 8][tx] = in[((size_t)b * C2c + c0 + ty + k * 8) * Ss + n0 + tx];
    __syncthreads();
#pragma unroll
    for (int k = 0; k < 4; k++) {
        int n = n0 + ty + k * 8;
        g_pts2t[((size_t)b * Ss + n) * C2c + c0 + tx] = tile[tx][ty + k * 8];
    }
}

// ------------------- transpose points1 [B,C1,N] -> g_feat cols 0..127 (fp32) ----------
__global__ void transpose_p1(const float* __restrict__ in) {
    __shared__ float tile[32][33];
    int b = blockIdx.z;
    int n0 = blockIdx.x * 32, c0 = blockIdx.y * 32;
    int tx = threadIdx.x, ty = threadIdx.y;
#pragma unroll
    for (int k = 0; k < 4; k++)
        tile[ty + k * 8][tx] = in[((size_t)b * C1c + c0 + ty + k * 8) * Nn + n0 + tx];
    __syncthreads();
#pragma unroll
    for (int k = 0; k < 4; k++) {
        int n = n0 + ty + k * 8;
        g_feat[((size_t)b * Nn + n) * CIN + c0 + tx] = tile[tx][ty + k * 8];
    }
}

// ------------------- kNN(3) + interp: 4 queries/warp, f32x2 scan, float4 gather -------
#define INS3(e, i, E0, E1, E2, I0, I1, I2)                         \
    if ((e) < (E2)) {                                              \
        if ((e) < (E1)) {                                          \
            E2 = E1; I2 = I1;                                      \
            if ((e) < (E0)) { E1 = E0; I1 = I0; E0 = (e); I0 = (i); } \
            else            { E1 = (e); I1 = (i); }                \
        } else { E2 = (e); I2 = (i); }                             \
    }

__global__ void knn_interp(const float* __restrict__ xyz1, const float* __restrict__ xyz2) {
    __shared__ float4 c4[Ss];
    int b = blockIdx.y;
    int n_base = blockIdx.x * 32;

    const float* x2 = xyz2 + (size_t)b * Ss * 3;
    for (int s = threadIdx.x; s < Ss; s += blockDim.x) {
        float x = x2[s * 3 + 0], y = x2[s * 3 + 1], z = x2[s * 3 + 2];
        c4[s] = make_float4(x, y, z, fmaf(x, x, fmaf(y, y, z * z)));
    }
    __syncthreads();

    int warp = threadIdx.x >> 5, lane = threadIdx.x & 31;
    int n0 = n_base + warp * 4;

    float qx[4], qy[4], qz[4], qsq[4];
#pragma unroll
    for (int q = 0; q < 4; q++) {
        const float* xq = xyz1 + ((size_t)b * Nn + n0 + q) * 3;
        qx[q] = xq[0]; qy[q] = xq[1]; qz[q] = xq[2];
        qsq[q] = fmaf(qx[q], qx[q], fmaf(qy[q], qy[q], qz[q] * qz[q]));
    }
    float2 X01 = {qx[0], qx[1]}, Y01 = {qy[0], qy[1]}, Z01 = {qz[0], qz[1]};
    float2 X23 = {qx[2], qx[3]}, Y23 = {qy[2], qy[3]}, Z23 = {qz[2], qz[3]};
    const float2 M2 = {-2.f, -2.f};
    const float2 Z2 = {0.f, 0.f};

    float E[4][3]; int I[4][3];
#pragma unroll
    for (int q = 0; q < 4; q++) {
        E[q][0] = E[q][1] = E[q][2] = 3.4e38f;
        I[q][0] = I[q][1] = I[q][2] = 0x7fffffff;
    }

#pragma unroll 4
    for (int s = lane; s < Ss; s += 32) {
        float4 c = c4[s];
        float2 CX = {c.x, c.x}, CY = {c.y, c.y}, CZ = {c.z, c.z}, CW = {c.w, c.w};
        float2 d01 = ffma2(X01, CX, ffma2(Y01, CY, ffma2(Z01, CZ, Z2)));
        float2 d23 = ffma2(X23, CX, ffma2(Y23, CY, ffma2(Z23, CZ, Z2)));
        float2 e01 = ffma2(M2, d01, CW);
        float2 e23 = ffma2(M2, d23, CW);
        INS3(e01.x, s, E[0][0], E[0][1], E[0][2], I[0][0], I[0][1], I[0][2]);
        INS3(e01.y, s, E[1][0], E[1][1], E[1][2], I[1][0], I[1][1], I[1][2]);
        INS3(e23.x, s, E[2][0], E[2][1], E[2][2], I[2][0], I[2][1], I[2][2]);
        INS3(e23.y, s, E[3][0], E[3][1], E[3][2], I[3][0], I[3][1], I[3][2]);
    }

#pragma unroll
    for (int q = 0; q < 4; q++) {
        int n = n0 + q;
        float be[3]; int bi[3];
        float h = E[q][0]; int hi = I[q][0]; int slot = 0;
        for (int k = 0; k < 3; k++) {
            float v = h; int vi = hi;
#pragma unroll
            for (int off = 16; off; off >>= 1) {
                float ov = __shfl_xor_sync(0xffffffffu, v, off);
                int   oi = __shfl_xor_sync(0xffffffffu, vi, off);
                if (ov < v || (ov == v && oi < vi)) { v = ov; vi = oi; }
            }
            be[k] = v; bi[k] = vi;
            if (h == v && hi == vi) {
                slot++;
                h  = (slot == 1) ? E[q][1] : E[q][2];
                hi = (slot == 1) ? I[q][1] : I[q][2];
            }
        }
        float d0 = fmaxf(be[0] + qsq[q], 0.f);
        float d1 = fmaxf(be[1] + qsq[q], 0.f);
        float d2 = fmaxf(be[2] + qsq[q], 0.f);
        float r0 = 1.f / (d0 + 1e-8f);
        float r1 = 1.f / (d1 + 1e-8f);
        float r2 = 1.f / (d2 + 1e-8f);
        float inv = 1.f / (r0 + r1 + r2);
        float w0 = r0 * inv, w1 = r1 * inv, w2 = r2 * inv;

        // float4 gather + interp (same arithmetic per element, 4x fewer issue slots)
        const float4* p0 = (const float4*)(g_pts2t + ((size_t)b * Ss + bi[0]) * C2c);
        const float4* p1 = (const float4*)(g_pts2t + ((size_t)b * Ss + bi[1]) * C2c);
        const float4* p2 = (const float4*)(g_pts2t + ((size_t)b * Ss + bi[2]) * C2c);
        float4* f4 = (float4*)(g_feat + ((size_t)b * Nn + n) * CIN + C1c);
#pragma unroll
        for (int j = 0; j < 2; j++) {
            int c = lane + 32 * j;
            float4 a0 = p0[c], a1 = p1[c], a2 = p2[c];
            float4 r;
            r.x = w0 * a0.x + w1 * a1.x + w2 * a2.x;
            r.y = w0 * a0.y + w1 * a1.y + w2 * a2.y;
            r.z = w0 * a0.z + w1 * a1.z + w2 * a2.z;
            r.w = w0 * a0.w + w1 * a1.w + w2 * a2.w;
            f4[c] = r;
        }
    }
}

// ------------------- GEMM via mma.sync bf16x3, k-slice 32, ldmatrix fragments ---------
// (R14 configuration verbatim: launch_bounds(512,1) — measured local optimum)
#define SR 40
#define BUFSZ 20480
#define OFF_AH 0
#define OFF_AL 5120
#define OFF_WH 10240
#define OFF_WL 15360
#define OFF_BIAS  81920
#define OFF_SCALE 82432
#define OFF_SHIFT 83456
#define GSM_BYTES 84480
template <int K, bool APPLY_BN, int LAYER>
__global__ void __launch_bounds__(512, 1) gemm_mma(const float* __restrict__ bias) {
    extern __shared__ char smc[];
    __nv_bfloat16* sm = (__nv_bfloat16*)smc;
    float* bias_s  = (float*)(smc + OFF_BIAS);
    float* scale_s = (float*)(smc + OFF_SCALE);
    float* shift_s = (float*)(smc + OFF_SHIFT);
    const uint32_t sbase = smem_u32(smc);

    const float* A = (LAYER == 0) ? g_feat : g_y1;
    const __nv_bfloat16* WH = (LAYER == 0) ? g_W1H : g_W2H;
    const __nv_bfloat16* WL = (LAYER == 0) ? g_W1L : g_W2L;
    float* C = (LAYER == 0) ? g_y1 : g_y2;

    const int tid = threadIdx.x;
    const int p0 = blockIdx.x * 128;
    const int m0 = blockIdx.y * 128;
    const int NS = K / 32;

    if (tid < 128) bias_s[tid] = bias[m0 + tid];
    if (APPLY_BN && tid < Hh) { scale_s[tid] = g_scale[0][tid]; shift_s[tid] = g_shift[0][tid]; }

    const int wrow = tid >> 2, wp = tid & 3;
    const int wid = tid >> 5, lane = tid & 31;
    const int wm = wid & 3;
    const int wn = wid >> 2;
    const int gid = lane >> 2, tig = lane & 3;

    const int li = lane & 7, lsel = lane >> 3;
    const int aoff0 = (wm * 32 + (lsel & 1) * 8 + li) * SR + (lsel >> 1) * 8;
    const int boff0 = (wn * 32 + li) * SR + ((lane >> 3) & 1) * 8;

    float acc[2][4][4];
#pragma unroll
    for (int a = 0; a < 2; a++)
#pragma unroll
        for (int b = 0; b < 4; b++)
#pragma unroll
            for (int c = 0; c < 4; c++) acc[a][b][c] = 0.f;

    __syncthreads();

    auto cvt4 = [&](float4 v, int kcol, uint2& H, uint2& L) {
        if (APPLY_BN) {
            v.x = fmaxf(fmaf(v.x, scale_s[kcol + 0], shift_s[kcol + 0]), 0.f);
            v.y = fmaxf(fmaf(v.y, scale_s[kcol + 1], shift_s[kcol + 1]), 0.f);
            v.z = fmaxf(fmaf(v.z, scale_s[kcol + 2], shift_s[kcol + 2]), 0.f);
            v.w = fmaxf(fmaf(v.w, scale_s[kcol + 3], shift_s[kcol + 3]), 0.f);
        }
        __nv_bfloat16 h0, h1, h2, h3, l0, l1, l2, l3;
        bf16split(v.x, h0, l0); bf16split(v.y, h1, l1);
        bf16split(v.z, h2, l2); bf16split(v.w, h3, l3);
        __nv_bfloat162 hp0 = {h0, h1}, hp1 = {h2, h3}, lp0 = {l0, l1}, lp1 = {l2, l3};
        H = make_uint2(*(uint32_t*)&hp0, *(uint32_t*)&hp1);
        L = make_uint2(*(uint32_t*)&lp0, *(uint32_t*)&lp1);
    };

    auto store_slice = [&](int kt0, int buf, const float4* pa, uint4 pwh, uint4 pwl) {
        int ob = buf * BUFSZ;
#pragma unroll
        for (int i = 0; i < 2; i++) {
            int idx = tid * 2 + i;
            int row = idx >> 3, c4 = idx & 7;
            uint2 H, L;
            cvt4(pa[i], kt0 + c4 * 4, H, L);
            *(uint2*)&sm[ob + OFF_AH + row * SR + c4 * 4] = H;
            *(uint2*)&sm[ob + OFF_AL + row * SR + c4 * 4] = L;
        }
        *(uint4*)&sm[ob + OFF_WH + wrow * SR + wp * 8] = pwh;
        *(uint4*)&sm[ob + OFF_WL + wrow * SR + wp * 8] = pwl;
    };

    {
        float4 pa[2];
#pragma unroll
        for (int i = 0; i < 2; i++) {
            int idx = tid * 2 + i;
            int row = idx >> 3, c4 = idx & 7;
            pa[i] = *(const float4*)&A[(size_t)(p0 + row) * K + c4 * 4];
        }
        uint4 pwh = *(const uint4*)&WH[(size_t)(m0 + wrow) * K + wp * 8];
        uint4 pwl = *(const uint4*)&WL[(size_t)(m0 + wrow) * K + wp * 8];
        store_slice(0, 0, pa, pwh, pwl);
    }
    __syncthreads();

    for (int ks = 0; ks < NS; ks++) {
        const int buf = ks & 1;
        const uint32_t abase = sbase + (uint32_t)(buf * BUFSZ) * 2;

        float4 pa[2]; uint4 pwh, pwl;
        const bool nxt = (ks + 1 < NS);
        if (nxt) {
            int k0 = (ks + 1) * 32;
#pragma unroll
            for (int i = 0; i < 2; i++) {
                int idx = tid * 2 + i;
                int row = idx >> 3, c4 = idx & 7;
                pa[i] = *(const float4*)&A[(size_t)(p0 + row) * K + k0 + c4 * 4];
            }
            pwh = *(const uint4*)&WH[(size_t)(m0 + wrow) * K + k0 + wp * 8];
            pwl = *(const uint4*)&WL[(size_t)(m0 + wrow) * K + k0 + wp * 8];
        }

#pragma unroll
        for (int kk = 0; kk < 2; kk++) {
            const int co = kk * 16;
            uint32_t aH[2][4], aL[2][4], bH[4][2], bL[4][2];
#pragma unroll
            for (int ma = 0; ma < 2; ma++) {
                uint32_t ao = (uint32_t)(aoff0 + ma * 16 * SR + co) * 2;
                ldsm_x4(aH[ma], abase + (OFF_AH * 2) + ao);
                ldsm_x4(aL[ma], abase + (OFF_AL * 2) + ao);
            }
#pragma unroll
            for (int na = 0; na < 4; na++) {
                uint32_t bo = (uint32_t)(boff0 + na * 8 * SR + co) * 2;
                ldsm_x2(bH[na], abase + (OFF_WH * 2) + bo);
                ldsm_x2(bL[na], abase + (OFF_WL * 2) + bo);
            }
#pragma unroll
            for (int ma = 0; ma < 2; ma++)
#pragma unroll
                for (int na = 0; na < 4; na++) {
                    mma16816(acc[ma][na], aH[ma], bH[na]);
                    mma16816(acc[ma][na], aH[ma], bL[na]);
                    mma16816(acc[ma][na], aL[ma], bH[na]);
                }
        }

        if (nxt) store_slice((ks + 1) * 32, buf ^ 1, pa, pwh, pwl);
        __syncthreads();
    }

    float* stg = (float*)smc;   // [128][132]
#pragma unroll
    for (int ma = 0; ma < 2; ma++)
#pragma unroll
        for (int na = 0; na < 4; na++) {
            int r = wm * 32 + ma * 16 + gid;
            int c = wn * 32 + na * 8 + tig * 2;
            float b0v = bias_s[c], b1v = bias_s[c + 1];
            stg[r * 132 + c]           = acc[ma][na][0] + b0v;
            stg[r * 132 + c + 1]       = acc[ma][na][1] + b1v;
            stg[(r + 8) * 132 + c]     = acc[ma][na][2] + b0v;
            stg[(r + 8) * 132 + c + 1] = acc[ma][na][3] + b1v;
        }
    __syncthreads();
#pragma unroll
    for (int it = 0; it < 8; it++) {
        int idx = tid + it * 512;
        int row = idx >> 5, c4i = idx & 31;
        float4 v = *(const float4*)&stg[row * 132 + c4i * 4];
        *(float4*)&C[(size_t)(p0 + row) * Hh + m0 + c4i * 4] = v;
    }
    if (tid < 128) {
        float s = 0.f, q = 0.f;
#pragma unroll 8
        for (int r = 0; r < 128; r++) {
            float v = stg[r * 132 + tid];
            s += v; q += v * v;
        }
        g_partS[LAYER][m0 + tid][blockIdx.x] = s;
        g_partQ[LAYER][m0 + tid][blockIdx.x] = q;
    }
}

// ------------------- BN stats -> per-channel scale/shift -------------------
template <int LAYER>
__global__ void bnstats(const float* __restrict__ gamma, const float* __restrict__ beta) {
    int m = threadIdx.x;
    float s = 0.f, q = 0.f;
#pragma unroll 8
    for (int i = 0; i < PT; i++) { s += g_partS[LAYER][m][i]; q += g_partQ[LAYER][m][i]; }
    const float invP = 1.f / (float)Pp;
    float mean = s * invP;
    float var = q * invP - mean * mean;
    float sc = gamma[m] * rsqrtf(var + 1e-5f);
    g_scale[LAYER][m] = sc;
    g_shift[LAYER][m] = beta[m] - mean * sc;
}

// ------------------- final: relu(bn2(y2)) -> out [B][256][N] (transpose) -------------
__global__ void bn_out(float* __restrict__ out) {
    __shared__ float tile[32][33];
    int b = blockIdx.z;
    int n0 = blockIdx.x * 32, m0 = blockIdx.y * 32;
    int tx = threadIdx.x, ty = threadIdx.y;
#pragma unroll
    for (int k = 0; k < 4; k++) {
        int nn = ty + k * 8;
        tile[nn][tx] = g_y2[((size_t)b * Nn + n0 + nn) * Hh + m0 + tx];
    }
    __syncthreads();
#pragma unroll
    for (int k = 0; k < 4; k++) {
        int m = m0 + ty + k * 8;
        float v = fmaxf(fmaf(tile[tx][ty + k * 8], g_scale[1][m], g_shift[1][m]), 0.f);
        out[(size_t)b * Hh * Nn + (size_t)m * Nn + n0 + tx] = v;
    }
}

// ------------------- launch -------------------
extern "C" void kernel_launch(void* const* d_in, const int* in_sizes, int n_in,
                              void* d_out, int out_size) {
    const float* xyz1    = (const float*)d_in[0];
    const float* xyz2    = (const float*)d_in[1];
    const float* points1 = (const float*)d_in[2];
    const float* points2 = (const float*)d_in[3];
    const float* W1      = (const float*)d_in[4];
    const float* b1      = (const float*)d_in[5];
    const float* gamma1  = (const float*)d_in[6];
    const float* beta1   = (const float*)d_in[7];
    const float* W2      = (const float*)d_in[8];
    const float* b2      = (const float*)d_in[9];
    const float* gamma2  = (const float*)d_in[10];
    const float* beta2   = (const float*)d_in[11];
    float* out = (float*)d_out;

    cudaFuncSetAttribute(gemm_mma<CIN, false, 0>, cudaFuncAttributeMaxDynamicSharedMemorySize, GSM_BYTES);
    cudaFuncSetAttribute(gemm_mma<Hh, true, 1>,  cudaFuncAttributeMaxDynamicSharedMemorySize, GSM_BYTES);

    dim3 tb(32, 8);
    wcvt<<<(Hh * CIN + 255) / 256, 256>>>(W1, W2);
    transpose_p2<<<dim3(Ss / 32, C2c / 32, Bb), tb>>>(points2);
    transpose_p1<<<dim3(Nn / 32, C1c / 32, Bb), tb>>>(points1);
    knn_interp<<<dim3(Nn / 32, Bb), 256>>>(xyz1, xyz2);
    gemm_mma<CIN, false, 0><<<dim3(PT, 2), 512, GSM_BYTES>>>(b1);
    bnstats<0><<<1, 256>>>(gamma1, beta1);
    gemm_mma<Hh, true, 1><<<dim3(PT, 2), 512, GSM_BYTES>>>(b2);
    bnstats<1><<<1, 256>>>(gamma2, beta2);
    bn_out<<<dim3(Nn / 32, Hh / 32, Bb), tb>>>(out);
    (void)in_sizes; (void)n_in; (void)out_size;
}